// round 2
// baseline (speedup 1.0000x reference)
#include <cuda_runtime.h>
#include <math.h>

// Problem constants (fixed by the dataset)
#define PN 2        // batch
#define PT 4096     // tokens
#define PD 300      // d_model
#define PH 6        // heads
#define PDH 50      // head dim
#define PTOPK 20
#define ZSPLIT 4    // q-range split for scores kernel

// Scratch (no cudaMalloc allowed)
__device__ float g_Q[PN * PT * PD];              // projected Q  [N*T, 300]
__device__ float g_K[PN * PT * PD];              // projected K  [N*T, 300]
__device__ float g_maxatt[ZSPLIT * PH * PN * PT]; // partial max over q, per z slice

// ---------------------------------------------------------------------------
// f32x2 packed-FMA helpers (Blackwell FFMA2 — 2 fp32 MACs per instruction)
// ---------------------------------------------------------------------------
typedef unsigned long long u64t;

__device__ __forceinline__ u64t bcast2(float v) {
    u64t r; unsigned u = __float_as_uint(v);
    asm("mov.b64 %0, {%1, %1};" : "=l"(r) : "r"(u));
    return r;
}
__device__ __forceinline__ void fma2(u64t& d, u64t a, u64t b) {
    asm("fma.rn.f32x2 %0, %1, %2, %0;" : "+l"(d) : "l"(a), "l"(b));
}
__device__ __forceinline__ float2 unpk2(u64t p) {
    unsigned lo, hi;
    asm("mov.b64 {%0, %1}, %2;" : "=r"(lo), "=r"(hi) : "l"(p));
    return make_float2(__uint_as_float(lo), __uint_as_float(hi));
}

// ---------------------------------------------------------------------------
// Kernel 1: projection GEMM  C[m,o] = sum_c X[m,c] * W[o,c]
// X:[8192,300], W:[300,300].  Tile 128m x 128o, 256 threads, microtile
// 8m(4 f32x2 pairs) x 8o(broadcast-packed). c streamed in 12 chunks of 25.
// grid: (8192/128=64, ceil(300/128)=3, 2)  z=0 -> Q, z=1 -> K
// ---------------------------------------------------------------------------
__global__ __launch_bounds__(256, 1) void proj_kernel(const float* __restrict__ Xq,
                                                      const float* __restrict__ Xk,
                                                      const float* __restrict__ Wq,
                                                      const float* __restrict__ Wk) {
    const float* X = (blockIdx.z == 0) ? Xq : Xk;
    const float* W = (blockIdx.z == 0) ? Wq : Wk;
    float* C       = (blockIdx.z == 0) ? g_Q : g_K;

    const int m0 = blockIdx.x * 128;
    const int o0 = blockIdx.y * 128;

    __shared__ __align__(16) float Xs[25][132];   // c-major [c][m]
    __shared__ __align__(16) float Ws[25][132];   // c-major [c][o]

    const int tid = threadIdx.x;
    const int tx  = tid & 15;     // -> o group
    const int ty  = tid >> 4;     // -> m group

    u64t acc[4][8];
#pragma unroll
    for (int p = 0; p < 4; ++p)
#pragma unroll
        for (int j = 0; j < 8; ++j) acc[p][j] = 0ULL;

    const int lrow  = tid & 127;
    const int lhalf = tid >> 7;
    const int cs    = lhalf ? 13 : 0;
    const int cnt   = lhalf ? 12 : 13;

    for (int cc = 0; cc < PD / 25; ++cc) {   // 12 chunks of 25
        __syncthreads();
        {
            const float* src = X + (size_t)(m0 + lrow) * PD + cc * 25 + cs;
#pragma unroll
            for (int i = 0; i < 13; ++i)
                if (i < cnt) Xs[cs + i][lrow] = src[i];
        }
        {
            const int o = o0 + lrow;
            const float* src = W + (size_t)o * PD + cc * 25 + cs;
#pragma unroll
            for (int i = 0; i < 13; ++i)
                if (i < cnt) Ws[cs + i][lrow] = (o < PD) ? src[i] : 0.f;
        }
        __syncthreads();

#pragma unroll 2
        for (int c = 0; c < 25; ++c) {
            const ulonglong2* xp = reinterpret_cast<const ulonglong2*>(&Xs[c][ty * 8]);
            const ulonglong2 xa = xp[0], xb = xp[1];
            u64t mp[4] = { xa.x, xa.y, xb.x, xb.y };

            const float4* qf = reinterpret_cast<const float4*>(&Ws[c][tx * 8]);
            const float4 qa = qf[0], qb = qf[1];
            u64t op[8] = { bcast2(qa.x), bcast2(qa.y), bcast2(qa.z), bcast2(qa.w),
                           bcast2(qb.x), bcast2(qb.y), bcast2(qb.z), bcast2(qb.w) };
#pragma unroll
            for (int p = 0; p < 4; ++p)
#pragma unroll
                for (int j = 0; j < 8; ++j)
                    fma2(acc[p][j], mp[p], op[j]);
        }
    }

#pragma unroll
    for (int p = 0; p < 4; ++p) {
        const int m = m0 + ty * 8 + 2 * p;
#pragma unroll
        for (int j = 0; j < 8; ++j) {
            const int o = o0 + tx * 8 + j;
            if (o < PD) {
                const float2 v = unpk2(acc[p][j]);
                C[(size_t)m * PD + o]       = v.x;
                C[(size_t)(m + 1) * PD + o] = v.y;
            }
        }
    }
}

// ---------------------------------------------------------------------------
// Kernel 2: partial maxatt[z][b][k] = max over q in z-slice of dot(Q_b[q], K_b[k])
// Tile: 256 keys (resident, 52KB dynamic smem) x 128 q streamed.
// 256 threads, microtile 16 keys (8 f32x2 pairs) x 8 q (broadcast-packed).
// grid: (4096/256=16, 12, ZSPLIT=4); each z handles 8 q-tiles of 128.
// ---------------------------------------------------------------------------
#define KS_STRIDE 260
#define QS_STRIDE 132
#define QS_BASE   (50 * KS_STRIDE)   // 13000 floats
#define SC_SMEM_FLOATS (QS_BASE + 25 * QS_STRIDE)   // 16300 floats = 65200 B

__global__ __launch_bounds__(256, 1) void scores_max_kernel() {
    extern __shared__ __align__(16) float sm[];

    const int kt   = blockIdx.x;
    const int b    = blockIdx.y;
    const int z    = blockIdx.z;
    const int head = b / PN;
    const int n    = b % PN;

    const float* Kbase = g_K + (size_t)n * PT * PD + head * PDH;
    const float* Qbase = g_Q + (size_t)n * PT * PD + head * PDH;

    const int tid = threadIdx.x;
    const int tx  = tid & 15;     // -> q group
    const int ty  = tid >> 4;     // -> key group (16 keys)

    // Load resident K tile: 256 keys x 50 c, c-major sm[c*260 + key]
    {
        const float* src = Kbase + (size_t)(kt * 256 + tid) * PD;
#pragma unroll 10
        for (int c = 0; c < PDH; ++c)
            sm[c * KS_STRIDE + tid] = src[c];
    }

    float kmL[8], kmH[8];
#pragma unroll
    for (int p = 0; p < 8; ++p) { kmL[p] = -3.0e38f; kmH[p] = -3.0e38f; }

    const int lrow  = tid & 127;
    const int lhalf = tid >> 7;
    const int cs    = lhalf ? 13 : 0;
    const int cnt   = lhalf ? 12 : 13;

    for (int qt = 0; qt < 8; ++qt) {
        const int q0 = (z * 8 + qt) * 128;

        u64t acc[8][8];
#pragma unroll
        for (int p = 0; p < 8; ++p)
#pragma unroll
            for (int j = 0; j < 8; ++j) acc[p][j] = 0ULL;

        for (int cc = 0; cc < 2; ++cc) {       // two 25-c chunks
            __syncthreads();                    // Qs reuse (and Ks readiness on iter 0)
            {
                const float* src = Qbase + (size_t)(q0 + lrow) * PD + cc * 25 + cs;
#pragma unroll
                for (int i = 0; i < 13; ++i)
                    if (i < cnt) sm[QS_BASE + (cs + i) * QS_STRIDE + lrow] = src[i];
            }
            __syncthreads();

#pragma unroll 2
            for (int c = 0; c < 25; ++c) {
                const ulonglong2* kp2 =
                    reinterpret_cast<const ulonglong2*>(&sm[(cc * 25 + c) * KS_STRIDE + ty * 16]);
                const ulonglong2 k0 = kp2[0], k1 = kp2[1], k2 = kp2[2], k3 = kp2[3];
                u64t kp[8] = { k0.x, k0.y, k1.x, k1.y, k2.x, k2.y, k3.x, k3.y };

                const float4* qf =
                    reinterpret_cast<const float4*>(&sm[QS_BASE + c * QS_STRIDE + tx * 8]);
                const float4 qa = qf[0], qb = qf[1];
                u64t qp[8] = { bcast2(qa.x), bcast2(qa.y), bcast2(qa.z), bcast2(qa.w),
                               bcast2(qb.x), bcast2(qb.y), bcast2(qb.z), bcast2(qb.w) };
#pragma unroll
                for (int p = 0; p < 8; ++p)
#pragma unroll
                    for (int j = 0; j < 8; ++j)
                        fma2(acc[p][j], kp[p], qp[j]);
            }
        }

        // fold this q-tile into the running per-key max
#pragma unroll
        for (int p = 0; p < 8; ++p)
#pragma unroll
            for (int j = 0; j < 8; ++j) {
                const float2 v = unpk2(acc[p][j]);
                kmL[p] = fmaxf(kmL[p], v.x);
                kmH[p] = fmaxf(kmH[p], v.y);
            }
    }

    // reduce across the 16 q-threads (tx) sharing each key group
#pragma unroll
    for (int off = 8; off; off >>= 1) {
#pragma unroll
        for (int p = 0; p < 8; ++p) {
            kmL[p] = fmaxf(kmL[p], __shfl_xor_sync(0xffffffffu, kmL[p], off));
            kmH[p] = fmaxf(kmH[p], __shfl_xor_sync(0xffffffffu, kmH[p], off));
        }
    }
    if (tx == 0) {
        const size_t base = ((size_t)z * (PH * PN) + b) * PT + kt * 256 + ty * 16;
#pragma unroll
        for (int p = 0; p < 8; ++p) {
            g_maxatt[base + 2 * p]     = kmL[p];
            g_maxatt[base + 2 * p + 1] = kmH[p];
        }
    }
}

// ---------------------------------------------------------------------------
// Kernel 3: fold z partials, top-20 (ties -> lowest index), softmax(scaled),
// weighted sum of gathered K rows. grid: 12 blocks x 256 threads.
// ---------------------------------------------------------------------------
__global__ __launch_bounds__(256) void select_kernel(float* __restrict__ out) {
    const int b    = blockIdx.x;
    const int head = b / PN;
    const int n    = b % PN;
    const int tid  = threadIdx.x;

    __shared__ float vals[PT];
    __shared__ float bestv[256];
    __shared__ int   besti[256];
    __shared__ float topv[PTOPK];
    __shared__ int   topi[PTOPK];
    __shared__ float probs[PTOPK];

    for (int i = tid; i < PT; i += 256) {
        float v = g_maxatt[(size_t)b * PT + i];
#pragma unroll
        for (int zz = 1; zz < ZSPLIT; ++zz)
            v = fmaxf(v, g_maxatt[((size_t)zz * (PH * PN) + b) * PT + i]);
        vals[i] = v;
    }
    __syncthreads();

    for (int sel = 0; sel < PTOPK; ++sel) {
        float bv = -3.0e38f;
        int   bi = 0x7fffffff;
        for (int i = tid; i < PT; i += 256) {
            const float v = vals[i];
            if (v > bv || (v == bv && i < bi)) { bv = v; bi = i; }
        }
        bestv[tid] = bv; besti[tid] = bi;
        __syncthreads();
        for (int s = 128; s; s >>= 1) {
            if (tid < s) {
                const float v2 = bestv[tid + s];
                const int   i2 = besti[tid + s];
                if (v2 > bestv[tid] || (v2 == bestv[tid] && i2 < besti[tid])) {
                    bestv[tid] = v2; besti[tid] = i2;
                }
            }
            __syncthreads();
        }
        if (tid == 0) {
            topv[sel] = bestv[0];
            topi[sel] = besti[0];
            vals[besti[0]] = -3.0e38f;
        }
        __syncthreads();
    }

    if (tid == 0) {
        const float inv = rsqrtf((float)PDH);     // 1/sqrt(50)
        float s = 0.f;
        float e[PTOPK];
#pragma unroll
        for (int i = 0; i < PTOPK; ++i) {
            e[i] = expf((topv[i] - topv[0]) * inv);
            s += e[i];
        }
        const float invs = 1.0f / s;
#pragma unroll
        for (int i = 0; i < PTOPK; ++i) probs[i] = e[i] * invs;
    }
    __syncthreads();

    for (int j = tid; j < PDH; j += 256) {
        float acc = 0.f;
#pragma unroll
        for (int i = 0; i < PTOPK; ++i)
            acc += probs[i] * g_K[((size_t)n * PT + topi[i]) * PD + head * PDH + j];
        out[(size_t)n * PD + head * PDH + j] = acc;
    }
}

// ---------------------------------------------------------------------------
extern "C" void kernel_launch(void* const* d_in, const int* in_sizes, int n_in,
                              void* d_out, int out_size) {
    const float* querys = (const float*)d_in[0];
    const float* keys   = (const float*)d_in[1];
    // d_in[2] = values : unused by reference output path
    const float* Wq     = (const float*)d_in[3];
    const float* Wk     = (const float*)d_in[4];
    // d_in[5] = Wv, d_in[6] = num_heads : unused / hardcoded

    dim3 gproj(PN * PT / 128, 3, 2);
    proj_kernel<<<gproj, 256>>>(querys, keys, Wq, Wk);

    cudaFuncSetAttribute(scores_max_kernel,
                         cudaFuncAttributeMaxDynamicSharedMemorySize,
                         SC_SMEM_FLOATS * (int)sizeof(float));
    dim3 gsc(PT / 256, PH * PN, ZSPLIT);
    scores_max_kernel<<<gsc, 256, SC_SMEM_FLOATS * sizeof(float)>>>();

    select_kernel<<<PH * PN, 256>>>((float*)d_out);
}

// round 4
// speedup vs baseline: 2.7653x; 2.7653x over previous
#include <cuda_runtime.h>
#include <cuda_bf16.h>
#include <math.h>
#include <stdint.h>

// Problem constants
#define PN 2
#define PT 4096
#define PD 300
#define PH 6
#define PDH 50
#define PTOPK 20
#define NB (PH * PN)   // 12
#define NCAND 64
#define NSLICE 16      // rescue q-slices
#define ZS 2           // scores q-split
#define KT 256         // keys per scores block
#define QCH 128        // q rows per chunk
#define RS 72          // padded smem row stride (bf16) -> 144B, conflict-free ldmatrix

#define CS 68          // proj smem stride (round-1 proven)

// Scratch (__device__ globals; zero-initialized once, pad columns never written)
__device__ float g_Q[PN * PT * PD];
__device__ float g_K[PN * PT * PD];
__device__ __nv_bfloat16 g_Qh[(size_t)NB * PT * 64];   // [b][t][64], cols 50..63 stay 0
__device__ __nv_bfloat16 g_Kh[(size_t)NB * PT * 64];
__device__ float g_maxapprox[ZS * NB * PT];
__device__ int   g_cand[NB * NCAND];
__device__ float g_exactpart[NB * NSLICE * NCAND];

// ---------------------------------------------------------------------------
// helpers
// ---------------------------------------------------------------------------
__device__ __forceinline__ uint32_t smem_u32(const void* p) {
    uint32_t a;
    asm("{ .reg .u64 t; cvta.to.shared.u64 t, %1; cvt.u32.u64 %0, t; }" : "=r"(a) : "l"(p));
    return a;
}

#define LDSM4(r, addr) \
    asm volatile("ldmatrix.sync.aligned.m8n8.x4.shared.b16 {%0,%1,%2,%3}, [%4];" \
                 : "=r"((r)[0]), "=r"((r)[1]), "=r"((r)[2]), "=r"((r)[3]) : "r"(addr))

#define MMA16816(d, a, br0, br1) \
    asm volatile("mma.sync.aligned.m16n8k16.row.col.f32.bf16.bf16.f32 " \
                 "{%0,%1,%2,%3}, {%4,%5,%6,%7}, {%8,%9}, {%0,%1,%2,%3};" \
                 : "+f"((d)[0]), "+f"((d)[1]), "+f"((d)[2]), "+f"((d)[3]) \
                 : "r"((a)[0]), "r"((a)[1]), "r"((a)[2]), "r"((a)[3]), "r"(br0), "r"(br1))

#define CP_ASYNC16(dst, src) \
    asm volatile("cp.async.cg.shared.global [%0], [%1], 16;" :: "r"(dst), "l"(src))
#define CP_COMMIT() asm volatile("cp.async.commit_group;" ::: "memory")
#define CP_WAIT1()  asm volatile("cp.async.wait_group 1;" ::: "memory")

// ---------------------------------------------------------------------------
// Kernel 1: projection GEMM (round-1 proven) + fused bf16 head-major epilogue
// C[m,o] = sum_c X[m,c]*W[o,c];  also emits g_{Q,K}h[(head*PN+n)*PT + t][o%50]
// ---------------------------------------------------------------------------
__global__ __launch_bounds__(256) void proj_kernel(const float* __restrict__ Xq,
                                                   const float* __restrict__ Xk,
                                                   const float* __restrict__ Wq,
                                                   const float* __restrict__ Wk) {
    const float* X = (blockIdx.z == 0) ? Xq : Xk;
    const float* W = (blockIdx.z == 0) ? Wq : Wk;
    float* C       = (blockIdx.z == 0) ? g_Q : g_K;
    __nv_bfloat16* Ch = (blockIdx.z == 0) ? g_Qh : g_Kh;

    const int m0 = blockIdx.x * 64;
    const int o0 = blockIdx.y * 64;

    __shared__ float Xs[PDH][CS];
    __shared__ float Ws[PDH][CS];

    const int tid   = threadIdx.x;
    const int lane8 = tid & 7;
    const int rowg  = tid >> 3;
    const int tx    = tid & 15;
    const int ty    = tid >> 4;

    float acc[4][4];
#pragma unroll
    for (int i = 0; i < 4; ++i)
#pragma unroll
        for (int j = 0; j < 4; ++j) acc[i][j] = 0.f;

    for (int kc = 0; kc < PD / PDH; ++kc) {
        __syncthreads();
#pragma unroll
        for (int pass = 0; pass < 2; ++pass) {
            const int r = rowg + 32 * pass;
            const float* xsrc = X + (size_t)(m0 + r) * PD + kc * PDH;
#pragma unroll
            for (int i = 0; i < 7; ++i) {
                const int c = lane8 + i * 8;
                if (c < PDH) Xs[c][r] = xsrc[c];
            }
            const int o = o0 + r;
            const float* wsrc = W + (size_t)o * PD + kc * PDH;
#pragma unroll
            for (int i = 0; i < 7; ++i) {
                const int c = lane8 + i * 8;
                if (c < PDH) Ws[c][r] = (o < PD) ? wsrc[c] : 0.f;
            }
        }
        __syncthreads();

#pragma unroll 10
        for (int c = 0; c < PDH; ++c) {
            const float4 xv = *reinterpret_cast<const float4*>(&Xs[c][ty * 4]);
            const float4 wv = *reinterpret_cast<const float4*>(&Ws[c][tx * 4]);
            acc[0][0] += xv.x * wv.x; acc[0][1] += xv.x * wv.y; acc[0][2] += xv.x * wv.z; acc[0][3] += xv.x * wv.w;
            acc[1][0] += xv.y * wv.x; acc[1][1] += xv.y * wv.y; acc[1][2] += xv.y * wv.z; acc[1][3] += xv.y * wv.w;
            acc[2][0] += xv.z * wv.x; acc[2][1] += xv.z * wv.y; acc[2][2] += xv.z * wv.z; acc[2][3] += xv.z * wv.w;
            acc[3][0] += xv.w * wv.x; acc[3][1] += xv.w * wv.y; acc[3][2] += xv.w * wv.z; acc[3][3] += xv.w * wv.w;
        }
    }

#pragma unroll
    for (int i = 0; i < 4; ++i) {
        const int m = m0 + ty * 4 + i;
        const int n = m >> 12;            // m / PT
        const int t = m & (PT - 1);
#pragma unroll
        for (int j = 0; j < 4; ++j) {
            const int o = o0 + tx * 4 + j;
            if (o < PD) {
                C[(size_t)m * PD + o] = acc[i][j];
                const int head = o / PDH;
                const int c    = o - head * PDH;
                Ch[((size_t)(head * PN + n) * PT + t) * 64 + c] =
                    __float2bfloat16_rn(acc[i][j]);
            }
        }
    }
}

// ---------------------------------------------------------------------------
// Kernel 2: approximate maxatt via warp-level bf16 HMMA.
// grid (PT/KT=16, NB=12, ZS=2), 256 threads.
// Warp w owns keys [32w, 32w+32) of the block's 256-key tile: two m16 A-tiles
// kept in registers. Q streamed in 128-row chunks (cp.async double buffer).
// maxatt accumulated as a running row-max; partial per z-slice.
// ---------------------------------------------------------------------------
__global__ __launch_bounds__(256, 1) void scores_mma_kernel() {
    extern __shared__ __align__(16) __nv_bfloat16 smq[];   // 2 stages x [128][RS]
    const int tid = threadIdx.x, w = tid >> 5, lane = tid & 31;
    const int kt = blockIdx.x, b = blockIdx.y, z = blockIdx.z;
    const uint32_t sq = smem_u32(smq);

    // Load K tile (256 keys x 64) into both stage buffers (rows 0..255)
    const __nv_bfloat16* Ktp = g_Kh + ((size_t)b * PT + kt * KT) * 64;
    for (int i = tid; i < KT * 8; i += 256) {
        const int row = i >> 3, ch = i & 7;
        *reinterpret_cast<float4*>(&smq[row * RS + ch * 8]) =
            *reinterpret_cast<const float4*>(Ktp + row * 64 + ch * 8);
    }
    __syncthreads();

    // A fragments: 2 m-tiles x 4 k-steps, canonical ldmatrix.x4 addressing
    uint32_t a[2][4][4];
    {
        const int r = lane & 15, ch = lane >> 4;
#pragma unroll
        for (int mt = 0; mt < 2; ++mt) {
            const uint32_t base =
                sq + (uint32_t)(((w * 32 + mt * 16 + r) * RS + ch * 8) * 2);
#pragma unroll
            for (int ks = 0; ks < 4; ++ks)
                LDSM4(a[mt][ks], base + ks * 32);
        }
    }
    __syncthreads();   // done reading K; stages may be overwritten by Q

    const __nv_bfloat16* Qbp = g_Qh + ((size_t)b * PT + (size_t)z * (PT / ZS)) * 64;
    const int NCH = (PT / ZS) / QCH;   // 16

    // prefetch chunk 0 into stage 0
    {
        const __nv_bfloat16* src = Qbp;
        for (int i = tid; i < QCH * 8; i += 256) {
            const int row = i >> 3, ch = i & 7;
            CP_ASYNC16(sq + (uint32_t)((row * RS + ch * 8) * 2), src + row * 64 + ch * 8);
        }
        CP_COMMIT();
    }

    float rm[2][2] = { { -3.0e38f, -3.0e38f }, { -3.0e38f, -3.0e38f } };

    for (int c = 0; c < NCH; ++c) {
        if (c + 1 < NCH) {
            const uint32_t dst0 = sq + (uint32_t)(((c + 1) & 1) * QCH * RS * 2);
            const __nv_bfloat16* src = Qbp + (size_t)(c + 1) * QCH * 64;
            for (int i = tid; i < QCH * 8; i += 256) {
                const int row = i >> 3, ch = i & 7;
                CP_ASYNC16(dst0 + (uint32_t)((row * RS + ch * 8) * 2), src + row * 64 + ch * 8);
            }
        }
        CP_COMMIT();
        CP_WAIT1();
        __syncthreads();

        const uint32_t qbase = sq + (uint32_t)((c & 1) * QCH * RS * 2);
#pragma unroll 4
        for (int nt = 0; nt < 16; ++nt) {
            const uint32_t baddr =
                qbase + (uint32_t)(((nt * 8 + (lane & 7)) * RS + (lane >> 3) * 8) * 2);
            uint32_t bf0[4], bf1[4];
            LDSM4(bf0, baddr);        // k 0..31  (ksteps 0,1)
            LDSM4(bf1, baddr + 64);   // k 32..63 (ksteps 2,3)
#pragma unroll
            for (int mt = 0; mt < 2; ++mt) {
                float d[4] = { 0.f, 0.f, 0.f, 0.f };
                MMA16816(d, a[mt][0], bf0[0], bf0[1]);
                MMA16816(d, a[mt][1], bf0[2], bf0[3]);
                MMA16816(d, a[mt][2], bf1[0], bf1[1]);
                MMA16816(d, a[mt][3], bf1[2], bf1[3]);
                rm[mt][0] = fmaxf(rm[mt][0], fmaxf(d[0], d[1]));
                rm[mt][1] = fmaxf(rm[mt][1], fmaxf(d[2], d[3]));
            }
        }
        __syncthreads();
    }

    // reduce over the 4 lanes sharing each row (same lane>>2)
#pragma unroll
    for (int mt = 0; mt < 2; ++mt)
#pragma unroll
        for (int h = 0; h < 2; ++h) {
            rm[mt][h] = fmaxf(rm[mt][h], __shfl_xor_sync(0xffffffffu, rm[mt][h], 1));
            rm[mt][h] = fmaxf(rm[mt][h], __shfl_xor_sync(0xffffffffu, rm[mt][h], 2));
        }
    if ((lane & 3) == 0) {
        const size_t base = ((size_t)z * NB + b) * PT + kt * KT + w * 32;
#pragma unroll
        for (int mt = 0; mt < 2; ++mt) {
            g_maxapprox[base + mt * 16 + (lane >> 2)]     = rm[mt][0];
            g_maxapprox[base + mt * 16 + (lane >> 2) + 8] = rm[mt][1];
        }
    }
}

// ---------------------------------------------------------------------------
// Kernel 3: top-64 candidates by approximate maxatt (12 blocks, shfl argmax)
// ---------------------------------------------------------------------------
__global__ __launch_bounds__(256) void cand_kernel() {
    const int b = blockIdx.x, tid = threadIdx.x, lane = tid & 31, wq = tid >> 5;
    __shared__ float vals[PT];
    __shared__ float wv[8];
    __shared__ int   wi[8];
    __shared__ int   sw;

    for (int i = tid; i < PT; i += 256)
        vals[i] = fmaxf(g_maxapprox[(size_t)b * PT + i],
                        g_maxapprox[((size_t)NB + b) * PT + i]);   // ZS=2 fold
    __syncthreads();

    float bv = -3.0e38f; int bi = 0x7fffffff;
    for (int i = tid; i < PT; i += 256) {
        const float v = vals[i];
        if (v > bv) { bv = v; bi = i; }
    }

    for (int sel = 0; sel < NCAND; ++sel) {
        float v = bv; int ix = bi;
#pragma unroll
        for (int off = 16; off; off >>= 1) {
            const float v2 = __shfl_xor_sync(0xffffffffu, v, off);
            const int   i2 = __shfl_xor_sync(0xffffffffu, ix, off);
            if (v2 > v || (v2 == v && i2 < ix)) { v = v2; ix = i2; }
        }
        if (lane == 0) { wv[wq] = v; wi[wq] = ix; }
        __syncthreads();
        if (wq == 0) {
            v = (lane < 8) ? wv[lane] : -3.0e38f;
            ix = (lane < 8) ? wi[lane] : 0x7fffffff;
#pragma unroll
            for (int off = 4; off; off >>= 1) {
                const float v2 = __shfl_xor_sync(0xffffffffu, v, off);
                const int   i2 = __shfl_xor_sync(0xffffffffu, ix, off);
                if (v2 > v || (v2 == v && i2 < ix)) { v = v2; ix = i2; }
            }
            if (lane == 0) {
                g_cand[b * NCAND + sel] = ix;
                vals[ix] = -3.0e38f;
                sw = ix;
            }
        }
        __syncthreads();
        if (bi == sw) {   // only the owner thread rescans its residue class
            bv = -3.0e38f; bi = 0x7fffffff;
            for (int i = tid; i < PT; i += 256) {
                const float v2 = vals[i];
                if (v2 > bv) { bv = v2; bi = i; }
            }
        }
    }
}

// ---------------------------------------------------------------------------
// Kernel 4: exact fp32 max over a q-slice for the 64 candidates.
// grid (12, NSLICE=16) x 256.  Candidate K row in registers; q broadcast.
// ---------------------------------------------------------------------------
__global__ __launch_bounds__(256) void rescue_kernel() {
    const int b = blockIdx.x, sl = blockIdx.y;
    const int head = b / PN, n = b % PN;
    const int tid = threadIdx.x;
    const int c = tid & 63, qg = tid >> 6;

    __shared__ int   cidx[NCAND];
    __shared__ float qs[8][56];
    __shared__ float part[256];

    if (tid < NCAND) cidx[tid] = g_cand[b * NCAND + tid];
    __syncthreads();

    float ck[PDH];
    {
        const float* kp = g_K + (size_t)(n * PT + cidx[c]) * PD + head * PDH;
#pragma unroll
        for (int j = 0; j < PDH; ++j) ck[j] = kp[j];
    }

    float mx = -3.0e38f;
    const int q0 = sl * (PT / NSLICE);   // 256 q per block

    for (int qc = 0; qc < (PT / NSLICE) / 8; ++qc) {   // 32 chunks of 8 rows
        for (int i = tid; i < 8 * PDH; i += 256) {
            const int r = i / PDH, j = i % PDH;
            qs[r][j] = g_Q[(size_t)(n * PT + q0 + qc * 8 + r) * PD + head * PDH + j];
        }
        __syncthreads();
#pragma unroll
        for (int rr = 0; rr < 2; ++rr) {
            const float* q = qs[qg * 2 + rr];
            float acc = 0.f;
#pragma unroll
            for (int jj = 0; jj < 12; ++jj) {
                const float4 qv = *reinterpret_cast<const float4*>(&q[jj * 4]);
                acc += ck[jj * 4 + 0] * qv.x + ck[jj * 4 + 1] * qv.y
                     + ck[jj * 4 + 2] * qv.z + ck[jj * 4 + 3] * qv.w;
            }
            acc += ck[48] * q[48] + ck[49] * q[49];
            mx = fmaxf(mx, acc);
        }
        __syncthreads();
    }
    part[tid] = mx;
    __syncthreads();
    if (tid < NCAND) {
        const float m = fmaxf(fmaxf(part[tid], part[tid + 64]),
                              fmaxf(part[tid + 128], part[tid + 192]));
        g_exactpart[(b * NSLICE + sl) * NCAND + tid] = m;
    }
}

// ---------------------------------------------------------------------------
// Kernel 5: fold slices, exact top-20 (tie -> lowest index), softmax, gather.
// ---------------------------------------------------------------------------
__global__ __launch_bounds__(64) void final_kernel(float* __restrict__ out) {
    const int b = blockIdx.x;
    const int head = b / PN, n = b % PN;
    const int tid = threadIdx.x;

    __shared__ float w[NCAND];
    __shared__ int   ci[NCAND];
    __shared__ float bvs[NCAND];
    __shared__ int   bis[NCAND];
    __shared__ float topv[PTOPK];
    __shared__ int   topi[PTOPK];
    __shared__ float probs[PTOPK];

    ci[tid] = g_cand[b * NCAND + tid];
    float e = -3.0e38f;
#pragma unroll
    for (int s = 0; s < NSLICE; ++s)
        e = fmaxf(e, g_exactpart[(b * NSLICE + s) * NCAND + tid]);
    w[tid] = e;
    __syncthreads();

    for (int sel = 0; sel < PTOPK; ++sel) {
        bvs[tid] = w[tid]; bis[tid] = ci[tid];
        __syncthreads();
        for (int s = 32; s; s >>= 1) {
            if (tid < s) {
                const float v2 = bvs[tid + s]; const int i2 = bis[tid + s];
                if (v2 > bvs[tid] || (v2 == bvs[tid] && i2 < bis[tid])) {
                    bvs[tid] = v2; bis[tid] = i2;
                }
            }
            __syncthreads();
        }
        if (tid == 0) { topv[sel] = bvs[0]; topi[sel] = bis[0]; }
        __syncthreads();
        if (ci[tid] == bis[0]) w[tid] = -3.0e38f;
        __syncthreads();
    }

    if (tid == 0) {
        const float inv = rsqrtf((float)PDH);
        float s = 0.f, ex[PTOPK];
#pragma unroll
        for (int i = 0; i < PTOPK; ++i) { ex[i] = expf((topv[i] - topv[0]) * inv); s += ex[i]; }
        const float invs = 1.0f / s;
#pragma unroll
        for (int i = 0; i < PTOPK; ++i) probs[i] = ex[i] * invs;
    }
    __syncthreads();

    for (int j = tid; j < PDH; j += 64) {
        float acc = 0.f;
#pragma unroll
        for (int i = 0; i < PTOPK; ++i)
            acc += probs[i] * g_K[(size_t)(n * PT + topi[i]) * PD + head * PDH + j];
        out[(size_t)n * PD + head * PDH + j] = acc;
    }
}

// ---------------------------------------------------------------------------
extern "C" void kernel_launch(void* const* d_in, const int* in_sizes, int n_in,
                              void* d_out, int out_size) {
    const float* querys = (const float*)d_in[0];
    const float* keys   = (const float*)d_in[1];
    const float* Wq     = (const float*)d_in[3];
    const float* Wk     = (const float*)d_in[4];

    dim3 gproj(PN * PT / 64, (PD + 63) / 64, 2);
    proj_kernel<<<gproj, 256>>>(querys, keys, Wq, Wk);

    const int scsmem = 2 * QCH * RS * 2;   // 36864 B
    dim3 gsc(PT / KT, NB, ZS);
    scores_mma_kernel<<<gsc, 256, scsmem>>>();

    cand_kernel<<<NB, 256>>>();
    rescue_kernel<<<dim3(NB, NSLICE), 256>>>();
    final_kernel<<<NB, NCAND>>>((float*)d_out);
}

// round 5
// speedup vs baseline: 2.9240x; 1.0574x over previous
#include <cuda_runtime.h>
#include <cuda_bf16.h>
#include <math.h>
#include <stdint.h>

// Problem constants
#define PN 2
#define PT 4096
#define PD 300
#define PH 6
#define PDH 50
#define PTOPK 20
#define NB (PH * PN)   // 12
#define NCAND 64
#define NQC 64         // rescue q-chunks (64 q rows each)
#define ZS 2           // scores q-split
#define KT 256         // keys per scores block
#define QCH 128        // q rows per chunk (scores)
#define RS 72          // scores smem row stride (bf16)

#define PST 24         // proj smem row stride (bf16) -> 48B, ldmatrix conflict-free
#define KSTEPS 19      // ceil(300/16)

// Scratch
__device__ float g_Q[PN * PT * PD];
__device__ float g_K[PN * PT * PD];
__device__ __nv_bfloat16 g_Qh[(size_t)NB * PT * 64];   // [b][t][64], cols 50..63 stay 0
__device__ __nv_bfloat16 g_Kh[(size_t)NB * PT * 64];
__device__ float g_maxapprox[ZS * NB * PT];
__device__ int   g_cand[NB * NCAND];
__device__ float g_exactpart[NB * NQC * NCAND];

// ---------------------------------------------------------------------------
// helpers
// ---------------------------------------------------------------------------
__device__ __forceinline__ uint32_t smem_u32(const void* p) {
    uint32_t a;
    asm("{ .reg .u64 t; cvta.to.shared.u64 t, %1; cvt.u32.u64 %0, t; }" : "=r"(a) : "l"(p));
    return a;
}

#define LDSM4(r, addr) \
    asm volatile("ldmatrix.sync.aligned.m8n8.x4.shared.b16 {%0,%1,%2,%3}, [%4];" \
                 : "=r"((r)[0]), "=r"((r)[1]), "=r"((r)[2]), "=r"((r)[3]) : "r"(addr))
#define LDSM2(r, addr) \
    asm volatile("ldmatrix.sync.aligned.m8n8.x2.shared.b16 {%0,%1}, [%2];" \
                 : "=r"((r)[0]), "=r"((r)[1]) : "r"(addr))

#define MMA16816(d, a, br0, br1) \
    asm volatile("mma.sync.aligned.m16n8k16.row.col.f32.bf16.bf16.f32 " \
                 "{%0,%1,%2,%3}, {%4,%5,%6,%7}, {%8,%9}, {%0,%1,%2,%3};" \
                 : "+f"((d)[0]), "+f"((d)[1]), "+f"((d)[2]), "+f"((d)[3]) \
                 : "r"((a)[0]), "r"((a)[1]), "r"((a)[2]), "r"((a)[3]), "r"(br0), "r"(br1))

#define CP_ASYNC16(dst, src) \
    asm volatile("cp.async.cg.shared.global [%0], [%1], 16;" :: "r"(dst), "l"(src))
#define CP_COMMIT() asm volatile("cp.async.commit_group;" ::: "memory")
#define CP_WAIT1()  asm volatile("cp.async.wait_group 1;" ::: "memory")

// ---------------------------------------------------------------------------
// Kernel 1: projection GEMM via bf16x3 HMMA (fp32-accurate emulation).
// C[m,o] = sum_k X[m,k] * W[o,k].  Block: 128m x 80o, 256 thr (8 warps 4x2),
// warp tile 32m x 40o (2 m16-tiles x 5 n8-tiles). k streamed in 16-steps.
// Split x = xh + xl (bf16 each); product = xh*wh + xh*wl + xl*wh.
// Epilogue: fp32 store + bf16 head-major store (cols 50..63 of g_*h stay 0).
// grid (8192/128=64, 4 n-blocks, 2 QK)
// ---------------------------------------------------------------------------
__global__ __launch_bounds__(256, 1) void proj_mma_kernel(const float* __restrict__ Xq,
                                                          const float* __restrict__ Xk,
                                                          const float* __restrict__ Wq,
                                                          const float* __restrict__ Wk) {
    const float* X = (blockIdx.z == 0) ? Xq : Xk;
    const float* W = (blockIdx.z == 0) ? Wq : Wk;
    float* C       = (blockIdx.z == 0) ? g_Q : g_K;
    __nv_bfloat16* Ch = (blockIdx.z == 0) ? g_Qh : g_Kh;

    const int m0 = blockIdx.x * 128;
    const int n0 = blockIdx.y * 80;

    __shared__ __align__(16) __nv_bfloat16 Xhi[128][PST];
    __shared__ __align__(16) __nv_bfloat16 Xlo[128][PST];
    __shared__ __align__(16) __nv_bfloat16 Whi[80][PST];
    __shared__ __align__(16) __nv_bfloat16 Wlo[80][PST];

    const int tid = threadIdx.x, w = tid >> 5, lane = tid & 31;
    const int wm = w >> 1, wn = w & 1;

    float acc[2][5][4];
#pragma unroll
    for (int mt = 0; mt < 2; ++mt)
#pragma unroll
        for (int nt = 0; nt < 5; ++nt)
#pragma unroll
            for (int j = 0; j < 4; ++j) acc[mt][nt][j] = 0.f;

    const uint32_t sxh = smem_u32(&Xhi[0][0]), sxl = smem_u32(&Xlo[0][0]);
    const uint32_t swh = smem_u32(&Whi[0][0]), swl = smem_u32(&Wlo[0][0]);

    for (int step = 0; step < KSTEPS; ++step) {
        const int k0 = step * 16;
        __syncthreads();
        // stage X: 128 rows x 16 k
        for (int idx = tid; idx < 128 * 16; idx += 256) {
            const int r = idx >> 4, kk = idx & 15;
            const int k = k0 + kk;
            const float v = (k < PD) ? X[(size_t)(m0 + r) * PD + k] : 0.f;
            const __nv_bfloat16 h = __float2bfloat16_rn(v);
            Xhi[r][kk] = h;
            Xlo[r][kk] = __float2bfloat16_rn(v - __bfloat162float(h));
        }
        // stage W: 80 rows x 16 k
        for (int idx = tid; idx < 80 * 16; idx += 256) {
            const int r = idx >> 4, kk = idx & 15;
            const int o = n0 + r, k = k0 + kk;
            const float v = (o < PD && k < PD) ? W[(size_t)o * PD + k] : 0.f;
            const __nv_bfloat16 h = __float2bfloat16_rn(v);
            Whi[r][kk] = h;
            Wlo[r][kk] = __float2bfloat16_rn(v - __bfloat162float(h));
        }
        __syncthreads();

        // A fragments (2 m-tiles, hi+lo)
        uint32_t ahi[2][4], alo[2][4];
        {
            const int r = lane & 15, ch = lane >> 4;
#pragma unroll
            for (int mt = 0; mt < 2; ++mt) {
                const uint32_t off = (uint32_t)(((wm * 32 + mt * 16 + r) * PST + ch * 8) * 2);
                LDSM4(ahi[mt], sxh + off);
                LDSM4(alo[mt], sxl + off);
            }
        }
        // B fragments (5 n-tiles, hi+lo)
        uint32_t bhi[5][2], blo[5][2];
        {
            const int sub = lane >> 3;                 // 0..3
            const int nofs = (sub >> 1) * 8, kofs = (sub & 1) * 8;
#pragma unroll
            for (int p = 0; p < 2; ++p) {
                const int row = wn * 40 + p * 16 + nofs + (lane & 7);
                const uint32_t off = (uint32_t)((row * PST + kofs) * 2);
                uint32_t t[4];
                LDSM4(t, swh + off);
                bhi[2 * p][0] = t[0]; bhi[2 * p][1] = t[1];
                bhi[2 * p + 1][0] = t[2]; bhi[2 * p + 1][1] = t[3];
                LDSM4(t, swl + off);
                blo[2 * p][0] = t[0]; blo[2 * p][1] = t[1];
                blo[2 * p + 1][0] = t[2]; blo[2 * p + 1][1] = t[3];
            }
            {
                const int row = wn * 40 + 32 + (lane & 7);
                const uint32_t off = (uint32_t)((row * PST + ((lane >> 3) & 1) * 8) * 2);
                LDSM2(bhi[4], swh + off);
                LDSM2(blo[4], swl + off);
            }
        }
#pragma unroll
        for (int mt = 0; mt < 2; ++mt)
#pragma unroll
            for (int nt = 0; nt < 5; ++nt) {
                MMA16816(acc[mt][nt], ahi[mt], bhi[nt][0], bhi[nt][1]);
                MMA16816(acc[mt][nt], ahi[mt], blo[nt][0], blo[nt][1]);
                MMA16816(acc[mt][nt], alo[mt], bhi[nt][0], bhi[nt][1]);
            }
    }

    // epilogue: d frag mapping — lane: rows (lane>>2), +8; cols (lane&3)*2, +1
#pragma unroll
    for (int mt = 0; mt < 2; ++mt) {
        const int mbase = m0 + wm * 32 + mt * 16 + (lane >> 2);
#pragma unroll
        for (int nt = 0; nt < 5; ++nt) {
            const int obase = n0 + wn * 40 + nt * 8 + (lane & 3) * 2;
#pragma unroll
            for (int j = 0; j < 4; ++j) {
                const int m = mbase + (j >> 1) * 8;
                const int o = obase + (j & 1);
                if (o < PD) {
                    const float v = acc[mt][nt][j];
                    C[(size_t)m * PD + o] = v;
                    const int n = m >> 12, t = m & (PT - 1);
                    const int head = o / PDH, c = o - head * PDH;
                    Ch[((size_t)(head * PN + n) * PT + t) * 64 + c] = __float2bfloat16_rn(v);
                }
            }
        }
    }
}

// ---------------------------------------------------------------------------
// Kernel 2: approximate maxatt via warp-level bf16 HMMA (proven R4 version).
// ---------------------------------------------------------------------------
__global__ __launch_bounds__(256, 1) void scores_mma_kernel() {
    extern __shared__ __align__(16) __nv_bfloat16 smq[];   // 2 stages x [128][RS]
    const int tid = threadIdx.x, w = tid >> 5, lane = tid & 31;
    const int kt = blockIdx.x, b = blockIdx.y, z = blockIdx.z;
    const uint32_t sq = smem_u32(smq);

    const __nv_bfloat16* Ktp = g_Kh + ((size_t)b * PT + kt * KT) * 64;
    for (int i = tid; i < KT * 8; i += 256) {
        const int row = i >> 3, ch = i & 7;
        *reinterpret_cast<float4*>(&smq[row * RS + ch * 8]) =
            *reinterpret_cast<const float4*>(Ktp + row * 64 + ch * 8);
    }
    __syncthreads();

    uint32_t a[2][4][4];
    {
        const int r = lane & 15, ch = lane >> 4;
#pragma unroll
        for (int mt = 0; mt < 2; ++mt) {
            const uint32_t base = sq + (uint32_t)(((w * 32 + mt * 16 + r) * RS + ch * 8) * 2);
#pragma unroll
            for (int ks = 0; ks < 4; ++ks)
                LDSM4(a[mt][ks], base + ks * 32);
        }
    }
    __syncthreads();

    const __nv_bfloat16* Qbp = g_Qh + ((size_t)b * PT + (size_t)z * (PT / ZS)) * 64;
    const int NCH = (PT / ZS) / QCH;   // 16

    {
        const __nv_bfloat16* src = Qbp;
        for (int i = tid; i < QCH * 8; i += 256) {
            const int row = i >> 3, ch = i & 7;
            CP_ASYNC16(sq + (uint32_t)((row * RS + ch * 8) * 2), src + row * 64 + ch * 8);
        }
        CP_COMMIT();
    }

    float rm[2][2] = { { -3.0e38f, -3.0e38f }, { -3.0e38f, -3.0e38f } };

    for (int c = 0; c < NCH; ++c) {
        if (c + 1 < NCH) {
            const uint32_t dst0 = sq + (uint32_t)(((c + 1) & 1) * QCH * RS * 2);
            const __nv_bfloat16* src = Qbp + (size_t)(c + 1) * QCH * 64;
            for (int i = tid; i < QCH * 8; i += 256) {
                const int row = i >> 3, ch = i & 7;
                CP_ASYNC16(dst0 + (uint32_t)((row * RS + ch * 8) * 2), src + row * 64 + ch * 8);
            }
        }
        CP_COMMIT();
        CP_WAIT1();
        __syncthreads();

        const uint32_t qbase = sq + (uint32_t)((c & 1) * QCH * RS * 2);
#pragma unroll 4
        for (int nt = 0; nt < 16; ++nt) {
            const uint32_t baddr =
                qbase + (uint32_t)(((nt * 8 + (lane & 7)) * RS + (lane >> 3) * 8) * 2);
            uint32_t bf0[4], bf1[4];
            LDSM4(bf0, baddr);
            LDSM4(bf1, baddr + 64);
#pragma unroll
            for (int mt = 0; mt < 2; ++mt) {
                float d[4] = { 0.f, 0.f, 0.f, 0.f };
                MMA16816(d, a[mt][0], bf0[0], bf0[1]);
                MMA16816(d, a[mt][1], bf0[2], bf0[3]);
                MMA16816(d, a[mt][2], bf1[0], bf1[1]);
                MMA16816(d, a[mt][3], bf1[2], bf1[3]);
                rm[mt][0] = fmaxf(rm[mt][0], fmaxf(d[0], d[1]));
                rm[mt][1] = fmaxf(rm[mt][1], fmaxf(d[2], d[3]));
            }
        }
        __syncthreads();
    }

#pragma unroll
    for (int mt = 0; mt < 2; ++mt)
#pragma unroll
        for (int h = 0; h < 2; ++h) {
            rm[mt][h] = fmaxf(rm[mt][h], __shfl_xor_sync(0xffffffffu, rm[mt][h], 1));
            rm[mt][h] = fmaxf(rm[mt][h], __shfl_xor_sync(0xffffffffu, rm[mt][h], 2));
        }
    if ((lane & 3) == 0) {
        const size_t base = ((size_t)z * NB + b) * PT + kt * KT + w * 32;
#pragma unroll
        for (int mt = 0; mt < 2; ++mt) {
            g_maxapprox[base + mt * 16 + (lane >> 2)]     = rm[mt][0];
            g_maxapprox[base + mt * 16 + (lane >> 2) + 8] = rm[mt][1];
        }
    }
}

// ---------------------------------------------------------------------------
// Kernel 3: top-64 candidates by approximate maxatt (12 blocks, shfl argmax)
// ---------------------------------------------------------------------------
__global__ __launch_bounds__(256) void cand_kernel() {
    const int b = blockIdx.x, tid = threadIdx.x, lane = tid & 31, wq = tid >> 5;
    __shared__ float vals[PT];
    __shared__ float wv[8];
    __shared__ int   wi[8];
    __shared__ int   sw;

    for (int i = tid; i < PT; i += 256)
        vals[i] = fmaxf(g_maxapprox[(size_t)b * PT + i],
                        g_maxapprox[((size_t)NB + b) * PT + i]);
    __syncthreads();

    float bv = -3.0e38f; int bi = 0x7fffffff;
    for (int i = tid; i < PT; i += 256) {
        const float v = vals[i];
        if (v > bv) { bv = v; bi = i; }
    }

    for (int sel = 0; sel < NCAND; ++sel) {
        float v = bv; int ix = bi;
#pragma unroll
        for (int off = 16; off; off >>= 1) {
            const float v2 = __shfl_xor_sync(0xffffffffu, v, off);
            const int   i2 = __shfl_xor_sync(0xffffffffu, ix, off);
            if (v2 > v || (v2 == v && i2 < ix)) { v = v2; ix = i2; }
        }
        if (lane == 0) { wv[wq] = v; wi[wq] = ix; }
        __syncthreads();
        if (wq == 0) {
            v = (lane < 8) ? wv[lane] : -3.0e38f;
            ix = (lane < 8) ? wi[lane] : 0x7fffffff;
#pragma unroll
            for (int off = 4; off; off >>= 1) {
                const float v2 = __shfl_xor_sync(0xffffffffu, v, off);
                const int   i2 = __shfl_xor_sync(0xffffffffu, ix, off);
                if (v2 > v || (v2 == v && i2 < ix)) { v = v2; ix = i2; }
            }
            if (lane == 0) {
                g_cand[b * NCAND + sel] = ix;
                vals[ix] = -3.0e38f;
                sw = ix;
            }
        }
        __syncthreads();
        if (bi == sw) {
            bv = -3.0e38f; bi = 0x7fffffff;
            for (int i = tid; i < PT; i += 256) {
                const float v2 = vals[i];
                if (v2 > bv) { bv = v2; bi = i; }
            }
        }
    }
}

// ---------------------------------------------------------------------------
// Kernel 4: exact fp32 per-candidate max over one 64-q chunk.
// grid (12, NQC=64) = 768 blocks, 256 threads. ONE stage barrier per block.
// ---------------------------------------------------------------------------
__global__ __launch_bounds__(256) void rescue_kernel() {
    const int b = blockIdx.x, qc = blockIdx.y;
    const int head = b / PN, n = b % PN;
    const int tid = threadIdx.x;
    const int c = tid & 63, qg = tid >> 6;    // candidate, q-subgroup (16 rows)

    __shared__ int   cidx[NCAND];
    __shared__ __align__(16) float qs[64][52];
    __shared__ float part[256];

    if (tid < NCAND) cidx[tid] = g_cand[b * NCAND + tid];
    __syncthreads();

    float ck[PDH];
    {
        const float* kp = g_K + (size_t)(n * PT + cidx[c]) * PD + head * PDH;
#pragma unroll
        for (int j = 0; j < PDH; ++j) ck[j] = kp[j];
    }

    const int q0 = qc * 64;
    for (int i = tid; i < 64 * PDH; i += 256) {
        const int r = i / PDH, j = i - r * PDH;
        qs[r][j] = g_Q[(size_t)(n * PT + q0 + r) * PD + head * PDH + j];
    }
    __syncthreads();

    float mx = -3.0e38f;
#pragma unroll 4
    for (int rr = 0; rr < 16; ++rr) {
        const float* q = qs[qg * 16 + rr];
        float acc = 0.f;
#pragma unroll
        for (int jj = 0; jj < 12; ++jj) {
            const float4 qv = *reinterpret_cast<const float4*>(&q[jj * 4]);
            acc += ck[jj * 4 + 0] * qv.x + ck[jj * 4 + 1] * qv.y
                 + ck[jj * 4 + 2] * qv.z + ck[jj * 4 + 3] * qv.w;
        }
        acc += ck[48] * q[48] + ck[49] * q[49];
        mx = fmaxf(mx, acc);
    }
    part[tid] = mx;
    __syncthreads();
    if (tid < NCAND) {
        const float m = fmaxf(fmaxf(part[tid], part[tid + 64]),
                              fmaxf(part[tid + 128], part[tid + 192]));
        g_exactpart[((size_t)b * NQC + qc) * NCAND + tid] = m;
    }
}

// ---------------------------------------------------------------------------
// Kernel 5: fold chunks, exact top-20 (tie -> lowest index), softmax, gather.
// ---------------------------------------------------------------------------
__global__ __launch_bounds__(64) void final_kernel(float* __restrict__ out) {
    const int b = blockIdx.x;
    const int head = b / PN, n = b % PN;
    const int tid = threadIdx.x;

    __shared__ float w[NCAND];
    __shared__ int   ci[NCAND];
    __shared__ float bvs[NCAND];
    __shared__ int   bis[NCAND];
    __shared__ float topv[PTOPK];
    __shared__ int   topi[PTOPK];
    __shared__ float probs[PTOPK];

    ci[tid] = g_cand[b * NCAND + tid];
    float e = -3.0e38f;
    for (int s = 0; s < NQC; ++s)
        e = fmaxf(e, g_exactpart[((size_t)b * NQC + s) * NCAND + tid]);
    w[tid] = e;
    __syncthreads();

    for (int sel = 0; sel < PTOPK; ++sel) {
        bvs[tid] = w[tid]; bis[tid] = ci[tid];
        __syncthreads();
        for (int s = 32; s; s >>= 1) {
            if (tid < s) {
                const float v2 = bvs[tid + s]; const int i2 = bis[tid + s];
                if (v2 > bvs[tid] || (v2 == bvs[tid] && i2 < bis[tid])) {
                    bvs[tid] = v2; bis[tid] = i2;
                }
            }
            __syncthreads();
        }
        if (tid == 0) { topv[sel] = bvs[0]; topi[sel] = bis[0]; }
        __syncthreads();
        if (ci[tid] == bis[0]) w[tid] = -3.0e38f;
        __syncthreads();
    }

    if (tid == 0) {
        const float inv = rsqrtf((float)PDH);
        float s = 0.f, ex[PTOPK];
#pragma unroll
        for (int i = 0; i < PTOPK; ++i) { ex[i] = expf((topv[i] - topv[0]) * inv); s += ex[i]; }
        const float invs = 1.0f / s;
#pragma unroll
        for (int i = 0; i < PTOPK; ++i) probs[i] = ex[i] * invs;
    }
    __syncthreads();

    for (int j = tid; j < PDH; j += 64) {
        float acc = 0.f;
#pragma unroll
        for (int i = 0; i < PTOPK; ++i)
            acc += probs[i] * g_K[(size_t)(n * PT + topi[i]) * PD + head * PDH + j];
        out[(size_t)n * PD + head * PDH + j] = acc;
    }
}

// ---------------------------------------------------------------------------
extern "C" void kernel_launch(void* const* d_in, const int* in_sizes, int n_in,
                              void* d_out, int out_size) {
    const float* querys = (const float*)d_in[0];
    const float* keys   = (const float*)d_in[1];
    const float* Wq     = (const float*)d_in[3];
    const float* Wk     = (const float*)d_in[4];

    dim3 gproj(PN * PT / 128, 4, 2);
    proj_mma_kernel<<<gproj, 256>>>(querys, keys, Wq, Wk);

    const int scsmem = 2 * QCH * RS * 2;   // 36864 B
    dim3 gsc(PT / KT, NB, ZS);
    scores_mma_kernel<<<gsc, 256, scsmem>>>();

    cand_kernel<<<NB, 256>>>();
    rescue_kernel<<<dim3(NB, NQC), 256>>>();
    final_kernel<<<NB, NCAND>>>((float*)d_out);
}